// round 9
// baseline (speedup 1.0000x reference)
#include <cuda_runtime.h>
#include <math.h>

#define NB 256      // batch size B
#define NE 8192     // epoch size E
#define NC 19       // classes C
#define NPAIR ((NC + 1) / 2)      // 10 class pairs (last is a singleton)
#define SPLIT 32                  // E-dim splits
#define CHUNK (NE / SPLIT)        // 256 == NB (one epoch row per thread)
#define NBLK (NPAIR * SPLIT)      // 320 blocks total

// ---------------- scratch (device globals; no allocations) ----------------
__device__ float d_posS[NC][NB];        // sorted ascending positive yp
__device__ float d_negS[NC][NB];        // sorted ascending negative yp
__device__ float d_P1[NC][NB + 1];      // exclusive prefix sums of pos values
__device__ float d_P2[NC][NB + 1];      // ... of pos squares
__device__ float d_N1[NC][NB + 1];      // ... of neg values
__device__ float d_N2[NC][NB + 1];      // ... of neg squares
__device__ int   d_np[NC];              // positives in current batch
__device__ int   d_capPart[NC][SPLIT];  // per-(class,split) epoch-positive counts
__device__ float d_pm2[NC][SPLIT];      // per-(class,split) partial m2
__device__ float d_pm3[NC][SPLIT];      // per-(class,split) partial m3
__device__ unsigned int d_bar;          // grid barrier counter (zero-init; reset in finalize)
__device__ unsigned int d_done;         // finalize counter   (zero-init; reset in finalize)

// block-wide inclusive scan (256 threads) via warp shuffles
__device__ __forceinline__ float block_scan_incl(float v, int t, float* s_w) {
    const int lane = t & 31, wid = t >> 5;
#pragma unroll
    for (int o = 1; o < 32; o <<= 1) {
        const float u = __shfl_up_sync(0xffffffffu, v, o);
        if (lane >= o) v += u;
    }
    if (lane == 31) s_w[wid] = v;
    __syncthreads();
    if (wid == 0) {
        float w = (lane < 8) ? s_w[lane] : 0.0f;
#pragma unroll
        for (int o = 1; o < 8; o <<= 1) {
            const float u = __shfl_up_sync(0xffffffffu, w, o);
            if (lane >= o) w += u;
        }
        if (lane < 8) s_w[lane] = w;
    }
    __syncthreads();
    const float res = v + ((wid > 0) ? s_w[wid - 1] : 0.0f);
    __syncthreads();   // s_w reused by next scan
    return res;
}

__device__ __forceinline__ void scan_store(float val, float* gdst, int t, float* s_w) {
    const float incl = block_scan_incl(val, t, s_w);
    gdst[t + 1] = incl;
    if (t == 0) gdst[0] = 0.0f;
}

// ---------------- fused single kernel: grid (NPAIR, SPLIT) ------------------
__global__ void __launch_bounds__(NB)
fused_kernel(const float* __restrict__ y_pred,
             const float* __restrict__ y_true,
             const float* __restrict__ epoch_pred,
             const float* __restrict__ epoch_true,
             const float* __restrict__ gamma,
             const float* __restrict__ rand_pos,
             const float* __restrict__ rand_neg,
             float* __restrict__ out) {
    const int pr = blockIdx.x;
    const int s  = blockIdx.y;
    const int t  = threadIdx.x;
    const int lane = t & 31, wid = t >> 5;
    const int c0 = 2 * pr;
    const bool has2 = (c0 + 1) < NC;
    const int c1 = has2 ? (c0 + 1) : c0;   // clamped (stores guarded)

    __shared__ float sp[2][NB], sn[2][NB];     // phase A: sort scratch; phase B: tables
    __shared__ float p1[2][NB + 1], p2[2][NB + 1], n1[2][NB + 1], n2[2][NB + 1];
    __shared__ float s_w[8];
    __shared__ unsigned char s_fl[NB];
    __shared__ int   s_ci[2][8];
    __shared__ float s_p[2], s_g[2];
    __shared__ int   s_npv[2];
    __shared__ float s_r[4][8];
    __shared__ float s_fin[32];
    __shared__ unsigned int s_rank;

    // ---- Phase A0: issue ALL epoch-side loads up-front (8-wide MLP; the
    //      class pair shares 32B sectors, so sector count == single class) --
    const int idx0 = (s * CHUNK + t) * NC + c0;
    const int idx1 = idx0 + (has2 ? 1 : 0);
    const float et0 = epoch_true[idx0];
    const float et1 = epoch_true[idx1];
    const float rp0 = rand_pos[idx0];
    const float rp1 = rand_pos[idx1];
    const float rn0 = rand_neg[idx0];
    const float rn1 = rand_neg[idx1];
    const float ep0 = epoch_pred[idx0];
    const float ep1 = epoch_pred[idx1];

    // ---- Phase A1: partial epoch-positive counts from registers ----
    int cnt0 = (et0 >= 0.5f) ? 1 : 0;
    int cnt1 = (et1 >= 0.5f) ? 1 : 0;
#pragma unroll
    for (int o = 16; o > 0; o >>= 1) {
        cnt0 += __shfl_down_sync(0xffffffffu, cnt0, o);
        cnt1 += __shfl_down_sync(0xffffffffu, cnt1, o);
    }
    if (lane == 0) { s_ci[0][wid] = cnt0; s_ci[1][wid] = cnt1; }
    __syncthreads();
    if (t == 0) {
        int a = 0, b = 0;
#pragma unroll
        for (int i = 0; i < 8; ++i) { a += s_ci[0][i]; b += s_ci[1][i]; }
        d_capPart[c0][s] = a;
        if (has2) d_capPart[c0 + 1][s] = b;
    }

    // ---- Phase A2: sort blocks (s==0 sorts c0; s==1 sorts c1) ----
    if (s == 0 || (s == 1 && has2)) {
        const int cs = (s == 0) ? c0 : (c0 + 1);
        const float yp = y_pred[t * NC + cs];
        const int isp = (y_true[t * NC + cs] >= 0.5f) ? 1 : 0;
        sp[0][t] = yp;                       // s_yp alias
        s_fl[t]  = (unsigned char)isp;
        sp[1][t] = 0.0f;                     // s_pos alias
        sn[0][t] = 0.0f;                     // s_neg alias
        __syncthreads();

        int rank = 0, np = 0;
#pragma unroll 8
        for (int i = 0; i < NB; ++i) {
            const int fi = (int)s_fl[i];
            const float v = sp[0][i];
            np += fi;
            if (fi == isp && (v < yp || (v == yp && i < t))) rank++;
        }
        __syncthreads();
        if (isp) sp[1][rank] = yp; else sn[0][rank] = yp;
        __syncthreads();

        const float pv = sp[1][t], nv = sn[0][t];
        d_posS[cs][t] = pv;
        d_negS[cs][t] = nv;
        scan_store(pv,      d_P1[cs], t, s_w);
        scan_store(pv * pv, d_P2[cs], t, s_w);
        scan_store(nv,      d_N1[cs], t, s_w);
        scan_store(nv * nv, d_N2[cs], t, s_w);
        if (t == 0) d_np[cs] = np;
    }

    // ---- grid barrier: publish, arrive, spin (all 320 blocks co-resident:
    //      ~12.5KB smem / 256 thr / ~40 regs -> >=6 blocks/SM, 320 << 888) --
    __threadfence();
    __syncthreads();
    if (t == 0) {
        atomicAdd(&d_bar, 1u);
        while (*((volatile unsigned int*)&d_bar) < NBLK) { __nanosleep(64); }
    }
    __syncthreads();
    __threadfence();

    // ---- Phase B0: caps (warp0 -> c0, warp1 -> c1; SPLIT==32 lanes) ----
    if (wid == 0) {
        int cp = d_capPart[c0][lane];
#pragma unroll
        for (int o = 16; o > 0; o >>= 1) cp += __shfl_down_sync(0xffffffffu, cp, o);
        if (lane == 0) {
            s_p[0]   = 1000.0f / fmaxf((float)cp, 1.0f);
            s_g[0]   = gamma[c0];
            s_npv[0] = d_np[c0];
        }
    } else if (wid == 1) {
        int cp = d_capPart[c1][lane];
#pragma unroll
        for (int o = 16; o > 0; o >>= 1) cp += __shfl_down_sync(0xffffffffu, cp, o);
        if (lane == 0) {
            s_p[1]   = 1000.0f / fmaxf((float)cp, 1.0f);
            s_g[1]   = gamma[c1];
            s_npv[1] = d_np[c1];
        }
    }

    // ---- Phase B1: table fill for both classes ----
    sp[0][t] = d_posS[c0][t];  sp[1][t] = d_posS[c1][t];
    sn[0][t] = d_negS[c0][t];  sn[1][t] = d_negS[c1][t];
    p1[0][t] = d_P1[c0][t];    p1[1][t] = d_P1[c1][t];
    p2[0][t] = d_P2[c0][t];    p2[1][t] = d_P2[c1][t];
    n1[0][t] = d_N1[c0][t];    n1[1][t] = d_N1[c1][t];
    n2[0][t] = d_N2[c0][t];    n2[1][t] = d_N2[c1][t];
    if (t == 0) {
#pragma unroll
        for (int k = 0; k < 2; ++k) {
            const int cc = k ? c1 : c0;
            p1[k][NB] = d_P1[cc][NB];
            p2[k][NB] = d_P2[cc][NB];
            n1[k][NB] = d_N1[cc][NB];
            n2[k][NB] = d_N2[cc][NB];
        }
    }
    __syncthreads();

    // ---- Phase B2: closed-form pairwise sums via binary search ----
    float m2[2] = {0.0f, 0.0f}, m3[2] = {0.0f, 0.0f};
#pragma unroll
    for (int k = 0; k < 2; ++k) {
        const float et = k ? et1 : et0;
        const float rp = k ? rp1 : rp0;
        const float rn = k ? rn1 : rn0;
        const float ep = k ? ep1 : ep0;
        const int np = s_npv[k];
        const int nn = NB - np;

        const bool isPos = et >= 0.5f;
        const float r = isPos ? rp : rn;
        if (r < s_p[k]) {
            const float g = s_g[k];
            const float key = isPos ? (ep - g) : (ep + g);
            const float* arr = isPos ? sn[k] : sp[k];
            const int n = isPos ? nn : np;
            int lo = 0, hi = n;
            while (lo < hi) {
                const int mid = (lo + hi) >> 1;
                const float v = arr[mid];
                const bool goR = isPos ? (v <= key) : (v < key);
                if (goR) lo = mid + 1; else hi = mid;
            }
            if (isPos) {
                // sum over batch negatives > key of (v - key)^2
                const float cntf = (float)(nn - lo);
                const float S1 = n1[k][nn] - n1[k][lo];
                const float S2 = n2[k][nn] - n2[k][lo];
                m3[k] = fmaf(fmaf(cntf, key, -2.0f * S1), key, S2);
            } else {
                // sum over batch positives < key of (key - v)^2
                const float kk = (float)lo;
                m2[k] = fmaf(fmaf(kk, key, -2.0f * p1[k][lo]), key, p2[k][lo]);
            }
        }
    }

    // ---- Phase B3: reduce + publish partials ----
#pragma unroll
    for (int o = 16; o > 0; o >>= 1) {
        m2[0] += __shfl_down_sync(0xffffffffu, m2[0], o);
        m3[0] += __shfl_down_sync(0xffffffffu, m3[0], o);
        m2[1] += __shfl_down_sync(0xffffffffu, m2[1], o);
        m3[1] += __shfl_down_sync(0xffffffffu, m3[1], o);
    }
    if (lane == 0) {
        s_r[0][wid] = m2[0];
        s_r[1][wid] = m3[0];
        s_r[2][wid] = m2[1];
        s_r[3][wid] = m3[1];
    }
    __syncthreads();

    if (t == 0) {
        float a0 = 0.0f, a1 = 0.0f, a2 = 0.0f, a3 = 0.0f;
#pragma unroll
        for (int i = 0; i < 8; ++i) {
            a0 += s_r[0][i]; a1 += s_r[1][i];
            a2 += s_r[2][i]; a3 += s_r[3][i];
        }
        d_pm2[c0][s] = a0;
        d_pm3[c0][s] = a1;
        if (has2) {
            d_pm2[c0 + 1][s] = a2;
            d_pm3[c0 + 1][s] = a3;
        }
        __threadfence();
        s_rank = atomicAdd(&d_done, 1u);
    }
    __syncthreads();

    // ---- last block finalizes and resets counters ----
    if (s_rank == NBLK - 1) {
        if (t < NC) {
            float res;
            const int cnp = d_np[t];
            if (cnp == 0 || cnp == NB) {
                res = (d_P1[t][NB] + d_N1[t][NB]) * 1e-8f;  // sum(yp) * 1e-8
            } else {
                float am2 = 0.0f, am3 = 0.0f;
#pragma unroll
                for (int q = 0; q < SPLIT; ++q) {
                    am2 += d_pm2[t][q];
                    am3 += d_pm3[t][q];
                }
                res = am2 * 1e-3f + am3 * 1e-3f;
                if (isnan(res)) res = 0.0f;
            }
            s_fin[t] = res;
        }
        __syncthreads();
        if (t == 0) {
            float acc = 0.0f;
#pragma unroll
            for (int q = 0; q < NC; ++q) acc += s_fin[q];
            out[0] = acc / (float)NC;
            d_done = 0;  // reset for next graph replay (deterministic)
            d_bar  = 0;
        }
    }
}

// ---------------- launch ----------------------------------------------------
extern "C" void kernel_launch(void* const* d_in, const int* in_sizes, int n_in,
                              void* d_out, int out_size) {
    const float* y_pred     = (const float*)d_in[0];
    const float* y_true     = (const float*)d_in[1];
    const float* epoch_pred = (const float*)d_in[2];
    const float* epoch_true = (const float*)d_in[3];
    const float* gamma      = (const float*)d_in[4];
    const float* rand_pos   = (const float*)d_in[5];
    const float* rand_neg   = (const float*)d_in[6];
    (void)in_sizes; (void)n_in; (void)out_size;

    dim3 grid(NPAIR, SPLIT);
    fused_kernel<<<grid, NB>>>(y_pred, y_true, epoch_pred, epoch_true,
                               gamma, rand_pos, rand_neg, (float*)d_out);
}